// round 7
// baseline (speedup 1.0000x reference)
#include <cuda_runtime.h>
#include <math.h>

#define BB 256
#define N_SV 64
#define N_TRK 512
#define N_PFC 512
#define KNN 8
#define HH 32

typedef unsigned long long u64;
typedef unsigned int u32;

// ---------------- scratch (static device arrays; no allocation) -------------
__device__ float g_sv [BB * N_SV  * HH];
__device__ float g_trk[BB * N_TRK * HH];
__device__ float g_pfc[BB * N_PFC * HH];
__device__ float g_U  [BB * N_TRK * HH];
__device__ float g_V  [BB * N_PFC * HH];
__device__ float g_V1 [BB * N_SV  * HH];
__device__ float g_f1 [BB * N_TRK * HH];
__device__ float g_f2 [BB * N_TRK * HH];
__device__ float g_f3 [BB * N_TRK * HH];

__device__ __forceinline__ float eluf(float x) {
    return x > 0.f ? x : (expf(x) - 1.f);
}

__device__ __forceinline__ void tf32split(float x, u32& h, u32& l) {
    asm("cvt.rna.tf32.f32 %0, %1;" : "=r"(h) : "f"(x));
    float r = x - __uint_as_float(h);
    asm("cvt.rna.tf32.f32 %0, %1;" : "=r"(l) : "f"(r));
}

__device__ __forceinline__ void mma_tf32(float& c0, float& c1, float& c2, float& c3,
                                         u32 a0, u32 a1, u32 a2, u32 a3,
                                         u32 b0, u32 b1)
{
    asm volatile(
        "mma.sync.aligned.m16n8k8.row.col.f32.tf32.tf32.f32 "
        "{%0,%1,%2,%3}, {%4,%5,%6,%7}, {%8,%9}, {%0,%1,%2,%3};"
        : "+f"(c0), "+f"(c1), "+f"(c2), "+f"(c3)
        : "r"(a0), "r"(a1), "r"(a2), "r"(a3), "r"(b0), "r"(b1));
}

// sorted ascending insert into 8-entry u64 list (sel[7] = worst kept)
#define SEL_INSERT(sel, c)                                          \
    if ((c) < sel[7]) {                                             \
        sel[7] = (c);                                               \
        _Pragma("unroll")                                           \
        for (int _p = 7; _p > 0; --_p) {                            \
            if (sel[_p] < sel[_p - 1]) {                            \
                u64 _t = sel[_p]; sel[_p] = sel[_p-1]; sel[_p-1] = _t; \
            }                                                       \
        }                                                           \
    }

// ================= fused encoder: 2-layer MLP, 128 nodes/block ==============
template <int FIN>
__device__ __forceinline__ void encode_body(
    const float* __restrict__ x,
    const float* __restrict__ W1, const float* __restrict__ b1,
    const float* __restrict__ W2, const float* __restrict__ b2,
    float* __restrict__ out, int blk,
    float* w1s, float* w2s, float* b1s, float* b2s)
{
    int tid = threadIdx.x;
    for (int i = tid; i < FIN * 32; i += 256) w1s[i] = W1[i];
    for (int i = tid; i < 1024;     i += 256) w2s[i] = W2[i];
    if (tid < 32) { b1s[tid] = b1[tid]; b2s[tid] = b2[tid]; }
    __syncthreads();

    int lane = tid & 31, wid = tid >> 5;

#pragma unroll
    for (int it = 0; it < 4; ++it) {
        int nb = blk * 128 + it * 32 + wid * 4;

        float xv0 = (lane < FIN) ? x[(size_t)(nb + 0) * FIN + lane] : 0.f;
        float xv1 = (lane < FIN) ? x[(size_t)(nb + 1) * FIN + lane] : 0.f;
        float xv2 = (lane < FIN) ? x[(size_t)(nb + 2) * FIN + lane] : 0.f;
        float xv3 = (lane < FIN) ? x[(size_t)(nb + 3) * FIN + lane] : 0.f;

        float h0 = b1s[lane], h1 = h0, h2 = h0, h3 = h0;
#pragma unroll
        for (int i = 0; i < FIN; ++i) {
            float w = w1s[i * 32 + lane];
            h0 = fmaf(__shfl_sync(0xffffffffu, xv0, i), w, h0);
            h1 = fmaf(__shfl_sync(0xffffffffu, xv1, i), w, h1);
            h2 = fmaf(__shfl_sync(0xffffffffu, xv2, i), w, h2);
            h3 = fmaf(__shfl_sync(0xffffffffu, xv3, i), w, h3);
        }
        h0 = eluf(h0); h1 = eluf(h1); h2 = eluf(h2); h3 = eluf(h3);

        float o0 = b2s[lane], o1 = o0, o2 = o0, o3 = o0;
#pragma unroll
        for (int i = 0; i < 32; ++i) {
            float w = w2s[i * 32 + lane];
            o0 = fmaf(__shfl_sync(0xffffffffu, h0, i), w, o0);
            o1 = fmaf(__shfl_sync(0xffffffffu, h1, i), w, o1);
            o2 = fmaf(__shfl_sync(0xffffffffu, h2, i), w, o2);
            o3 = fmaf(__shfl_sync(0xffffffffu, h3, i), w, o3);
        }
        out[(size_t)(nb + 0) * 32 + lane] = eluf(o0);
        out[(size_t)(nb + 1) * 32 + lane] = eluf(o1);
        out[(size_t)(nb + 2) * 32 + lane] = eluf(o2);
        out[(size_t)(nb + 3) * 32 + lane] = eluf(o3);
    }
}

__global__ void __launch_bounds__(256) encode_all_k(
    const float* x_sv, const float* x_trk, const float* x_pfc,
    const float* svW1, const float* svb1, const float* svW2, const float* svb2,
    const float* tkW1, const float* tkb1, const float* tkW2, const float* tkb2,
    const float* pfW1, const float* pfb1, const float* pfW2, const float* pfb2,
    float* o_sv, float* o_trk, float* o_pfc)
{
    __shared__ float w1s[32 * 32];
    __shared__ float w2s[32 * 32];
    __shared__ float b1s[32], b2s[32];
    int b = blockIdx.x;
    if (b < 128)
        encode_body<14>(x_sv, svW1, svb1, svW2, svb2, o_sv, b, w1s, w2s, b1s, b2s);
    else if (b < 1152)
        encode_body<30>(x_trk, tkW1, tkb1, tkW2, tkb2, o_trk, b - 128, w1s, w2s, b1s, b2s);
    else
        encode_body<10>(x_pfc, pfW1, pfb1, pfW2, pfb2, o_pfc, b - 1152, w1s, w2s, b1s, b2s);
}

// ================ fused 32x32 linear (mode 0: (Wa-Wb)+b, mode 1: Wb) ========
__device__ __forceinline__ void lin_body(
    const float* __restrict__ in, float* __restrict__ out, int blk, int mode,
    const float* __restrict__ convW, const float* __restrict__ convB,
    float* ws, float* bs)
{
    int tid = threadIdx.x;
    for (int i = tid; i < 1024; i += 256)
        ws[i] = (mode == 0) ? (convW[i] - convW[1024 + i]) : convW[1024 + i];
    if (tid < 32) bs[tid] = (mode == 0) ? convB[tid] : 0.f;
    __syncthreads();

    int lane = tid & 31, wid = tid >> 5;

#pragma unroll
    for (int it = 0; it < 4; ++it) {
        int nb = blk * 128 + it * 32 + wid * 4;

        float xv0 = in[(size_t)(nb + 0) * 32 + lane];
        float xv1 = in[(size_t)(nb + 1) * 32 + lane];
        float xv2 = in[(size_t)(nb + 2) * 32 + lane];
        float xv3 = in[(size_t)(nb + 3) * 32 + lane];
        float o0 = bs[lane], o1 = o0, o2 = o0, o3 = o0;
#pragma unroll
        for (int i = 0; i < 32; ++i) {
            float w = ws[i * 32 + lane];
            o0 = fmaf(__shfl_sync(0xffffffffu, xv0, i), w, o0);
            o1 = fmaf(__shfl_sync(0xffffffffu, xv1, i), w, o1);
            o2 = fmaf(__shfl_sync(0xffffffffu, xv2, i), w, o2);
            o3 = fmaf(__shfl_sync(0xffffffffu, xv3, i), w, o3);
        }
        out[(size_t)(nb + 0) * 32 + lane] = o0;
        out[(size_t)(nb + 1) * 32 + lane] = o1;
        out[(size_t)(nb + 2) * 32 + lane] = o2;
        out[(size_t)(nb + 3) * 32 + lane] = o3;
    }
}

__global__ void __launch_bounds__(256) lin_all_k(
    const float* sv, const float* trk, const float* pfc,
    float* V1, float* U, float* V,
    const float* convW, const float* convB)
{
    __shared__ float ws[1024];
    __shared__ float bs[32];
    int b = blockIdx.x;
    if (b < 128)        lin_body(sv,  V1, b,        1, convW, convB, ws, bs);
    else if (b < 1152)  lin_body(trk, U,  b - 128,  0, convW, convB, ws, bs);
    else                lin_body(pfc, V,  b - 1152, 1, convW, convB, ws, bs);
}

__global__ void __launch_bounds__(256) lin2_k(
    const float* f1, const float* f2, float* V, float* U,
    const float* convW, const float* convB)
{
    __shared__ float ws[1024];
    __shared__ float bs[32];
    int b = blockIdx.x;
    if (b < 1024) lin_body(f1, V, b,        1, convW, convB, ws, bs);
    else          lin_body(f2, U, b - 1024, 0, convW, convB, ws, bs);
}

// ================= kNN via split-tf32 mma + buffered selection ==============
// 2 blocks/event (256 dsts each), 512 threads = 16 warps, m16 dst-tile/warp.
// Scores by mma (hi*hi + hi*lo + lo*hi); selection by branch-free predicated
// appends into a per-lane smem buffer with rare warp-uniform flushes.
// Candidate u64 = (f32bits(max(d2,0)) << 32) | src_idx  (exact, stable).
//
// smem (92416 B): idxs 8K | srcT_hi 9216 | srcT_lo 9216 | sq 256 | buf 64K
// buf doubles as the final dump region for the 4-lane exact merge.
#define CH       64
#define CAPK     8
#define SM_IDX   0
#define SM_HI    8192
#define SM_LO    (8192 + 9216)
#define SM_SQ    (8192 + 18432)
#define SM_BUF   (8192 + 18688)
#define KNN_SMEM (SM_BUF + 512 * 2 * CAPK * 8)

__device__ __forceinline__ void flush_u64(const u64* mybuf, int& cnt, u64 (&sel)[8])
{
    for (int i = 0; i < cnt; ++i) {
        u64 c = mybuf[i];
        SEL_INSERT(sel, c);
    }
    cnt = 0;
}

__global__ void __launch_bounds__(512, 1) knn_k(
                      const float* __restrict__ src_enc,
                      const float* __restrict__ dst_enc,
                      const float* __restrict__ V,
                      const float* __restrict__ U,
                      float* __restrict__ out, int Ns)
{
    extern __shared__ char smraw[];
    int*   idxs    = (int*)(smraw + SM_IDX);
    float* srcT_hi = (float*)(smraw + SM_HI);    // [32][72]
    float* srcT_lo = (float*)(smraw + SM_LO);    // [32][72]
    float* sqs     = (float*)(smraw + SM_SQ);    // [64]
    u64*   buf     = (u64*)(smraw + SM_BUF);     // 512 thr x 2 rows x CAPK

    int tid  = threadIdx.x;
    int lane = tid & 31;
    int w    = tid >> 5;          // 0..15
    int e    = blockIdx.x >> 1;
    int half = blockIdx.x & 1;
    int g    = lane >> 2;         // 0..7
    int c4   = lane & 3;          // 0..3

    const float* sbase = src_enc + (size_t)e * Ns * 32;
    int dstbase = half * 256 + w * 16;
    const float* dbase = dst_enc + ((size_t)e * 512 + dstbase) * 32;

    // ---- A fragments (persist): rows g / g+8 of this warp's 16-dst tile ----
    u32 ahi[16], alo[16];
    float sd0 = 0.f, sd1 = 0.f;
#pragma unroll
    for (int j = 0; j < 4; ++j) {
        int k = 8 * j + c4;
        float x00 = dbase[g * 32 + k];
        float x10 = dbase[(g + 8) * 32 + k];
        float x01 = dbase[g * 32 + k + 4];
        float x11 = dbase[(g + 8) * 32 + k + 4];
        sd0 = fmaf(x00, x00, sd0); sd0 = fmaf(x01, x01, sd0);
        sd1 = fmaf(x10, x10, sd1); sd1 = fmaf(x11, x11, sd1);
        tf32split(x00, ahi[4*j+0], alo[4*j+0]);
        tf32split(x10, ahi[4*j+1], alo[4*j+1]);
        tf32split(x01, ahi[4*j+2], alo[4*j+2]);
        tf32split(x11, ahi[4*j+3], alo[4*j+3]);
    }
    sd0 += __shfl_xor_sync(0xffffffffu, sd0, 1);
    sd0 += __shfl_xor_sync(0xffffffffu, sd0, 2);
    sd1 += __shfl_xor_sync(0xffffffffu, sd1, 1);
    sd1 += __shfl_xor_sync(0xffffffffu, sd1, 2);

    u64 sel0[8], sel1[8];
#pragma unroll
    for (int k = 0; k < 8; ++k) { sel0[k] = ~0ull; sel1[k] = ~0ull; }

    int cnt0 = 0, cnt1 = 0;
    u64* mybuf0 = buf + (size_t)tid * 2 * CAPK;
    u64* mybuf1 = mybuf0 + CAPK;
    unsigned buf0_sa = (unsigned)__cvta_generic_to_shared(mybuf0);
    unsigned buf1_sa = (unsigned)__cvta_generic_to_shared(mybuf1);

    // ---- chunked src streaming (CH=64) ----
    int nch = (Ns + CH - 1) / CH;
    for (int ch = 0; ch < nch; ++ch) {
        int cbase = ch * CH;

        __syncthreads();
        // stage: warp per src; lane = dim
        for (int sl = w; sl < CH; sl += 16) {
            float x = sbase[(size_t)(cbase + sl) * 32 + lane];
            u32 h, l;
            tf32split(x, h, l);
            srcT_hi[lane * 72 + sl] = __uint_as_float(h);
            srcT_lo[lane * 72 + sl] = __uint_as_float(l);
            float v = x * x;
#pragma unroll
            for (int o = 16; o; o >>= 1) v += __shfl_xor_sync(0xffffffffu, v, o);
            if (lane == 0) sqs[sl] = v;
        }
        __syncthreads();

        for (int st = 0; st < CH / 8; ++st) {
            int sl0 = st << 3;
            float c0 = 0.f, c1 = 0.f, c2 = 0.f, c3 = 0.f;
#pragma unroll
            for (int j = 0; j < 4; ++j) {
                int k = 8 * j + c4;
                int off = k * 72 + sl0 + g;
                u32 bh0 = __float_as_uint(srcT_hi[off]);
                u32 bh1 = __float_as_uint(srcT_hi[off + 4 * 72]);
                u32 bl0 = __float_as_uint(srcT_lo[off]);
                u32 bl1 = __float_as_uint(srcT_lo[off + 4 * 72]);
                mma_tf32(c0, c1, c2, c3, ahi[4*j+0], ahi[4*j+1], ahi[4*j+2], ahi[4*j+3], bh0, bh1);
                mma_tf32(c0, c1, c2, c3, ahi[4*j+0], ahi[4*j+1], ahi[4*j+2], ahi[4*j+3], bl0, bl1);
                mma_tf32(c0, c1, c2, c3, alo[4*j+0], alo[4*j+1], alo[4*j+2], alo[4*j+3], bh0, bh1);
            }
            // epilogue: d2 = sd + sq - 2*xy (clamped), pack, branch-free append
            float2 sqp = *(const float2*)(sqs + sl0 + 2 * c4);
            float t00 = sd0 + sqp.x, t01 = sd0 + sqp.y;
            float t10 = sd1 + sqp.x, t11 = sd1 + sqp.y;
            float d00 = fmaxf(fmaf(-2.f, c0, t00), 0.f);
            float d01 = fmaxf(fmaf(-2.f, c1, t01), 0.f);
            float d10 = fmaxf(fmaf(-2.f, c2, t10), 0.f);
            float d11 = fmaxf(fmaf(-2.f, c3, t11), 0.f);
            unsigned sE = (unsigned)(cbase + sl0 + 2 * c4);
            u64 p00 = ((u64)__float_as_uint(d00) << 32) | sE;
            u64 p01 = ((u64)__float_as_uint(d01) << 32) | (sE + 1);
            u64 p10 = ((u64)__float_as_uint(d10) << 32) | sE;
            u64 p11 = ((u64)__float_as_uint(d11) << 32) | (sE + 1);

            asm volatile("{.reg .pred p; setp.lt.u64 p, %1, %2; @p st.shared.b64 [%0], %1;}"
                :: "r"(buf0_sa + (unsigned)cnt0 * 8u), "l"(p00), "l"(sel0[7]) : "memory");
            cnt0 += (p00 < sel0[7]) ? 1 : 0;
            asm volatile("{.reg .pred p; setp.lt.u64 p, %1, %2; @p st.shared.b64 [%0], %1;}"
                :: "r"(buf0_sa + (unsigned)cnt0 * 8u), "l"(p01), "l"(sel0[7]) : "memory");
            cnt0 += (p01 < sel0[7]) ? 1 : 0;
            asm volatile("{.reg .pred p; setp.lt.u64 p, %1, %2; @p st.shared.b64 [%0], %1;}"
                :: "r"(buf1_sa + (unsigned)cnt1 * 8u), "l"(p10), "l"(sel1[7]) : "memory");
            cnt1 += (p10 < sel1[7]) ? 1 : 0;
            asm volatile("{.reg .pred p; setp.lt.u64 p, %1, %2; @p st.shared.b64 [%0], %1;}"
                :: "r"(buf1_sa + (unsigned)cnt1 * 8u), "l"(p11), "l"(sel1[7]) : "memory");
            cnt1 += (p11 < sel1[7]) ? 1 : 0;

            // warp-uniform flush check; <=4 appends/row/tile so CAPK=8 is safe
            if (__any_sync(0xffffffffu, (cnt0 >= CAPK - 3) | (cnt1 >= CAPK - 3))) {
                flush_u64(mybuf0, cnt0, sel0);
                flush_u64(mybuf1, cnt1, sel1);
            }
        }
    }
    flush_u64(mybuf0, cnt0, sel0);
    flush_u64(mybuf1, cnt1, sel1);

    // ---- dump per-lane lists into buf region, 4-lane exact merge ----
    __syncthreads();
    {
        u64* myd = buf + (size_t)tid * 2 * CAPK;
#pragma unroll
        for (int k = 0; k < 8; ++k) { myd[k] = sel0[k]; myd[CAPK + k] = sel1[k]; }
    }
    __syncthreads();

    if (tid < 256) {
        int d = tid;
        int dw = d >> 4;             // owning warp
        int r  = d & 15;             // row in tile
        int slot = r >> 3;           // 0: rows 0-7 (sel0), 1: rows 8-15 (sel1)
        int lg = (r & 7) * 4;        // first owner lane
        u64 m[8];
        const u64* l0 = buf + ((size_t)(dw * 32 + lg) * 2 + slot) * CAPK;
#pragma unroll
        for (int k = 0; k < 8; ++k) m[k] = l0[k];
#pragma unroll
        for (int li = 1; li < 4; ++li) {
            const u64* ll = buf + ((size_t)(dw * 32 + lg + li) * 2 + slot) * CAPK;
#pragma unroll
            for (int k = 0; k < 8; ++k) {
                u64 c = ll[k];
                SEL_INSERT(m, c);
            }
        }
#pragma unroll
        for (int k = 0; k < 8; ++k)
            idxs[d * 8 + k] = (int)(u32)m[k];
    }
    __syncthreads();

    // ---- aggregation: warp per dst, coalesced V gathers ----
    const float* Ve = V + (size_t)e * Ns * 32;
    for (int dd = w; dd < 256; dd += 16) {
        int dg = e * 512 + half * 256 + dd;
        float mx = -3.4e38f;
#pragma unroll
        for (int k = 0; k < KNN; ++k) {
            int s = idxs[dd * 8 + k];
            mx = fmaxf(mx, Ve[s * 32 + lane]);
        }
        out[(size_t)dg * 32 + lane] = eluf(U[(size_t)dg * 32 + lane] + mx);
    }
}

// ---------------- mean pool + head MLP + sigmoid -----------------------------
__global__ void pool_k(const float* __restrict__ f3,
                       const float* __restrict__ W1, const float* __restrict__ b1,
                       const float* __restrict__ W2, const float* __restrict__ b2,
                       float* __restrict__ out, int out_size)
{
    int e = blockIdx.x;
    int tid = threadIdx.x;
    int j = tid & 31, g = tid >> 5;
    const float* base = f3 + (size_t)e * 512 * 32;
    float acc = 0.f;
    for (int r = g; r < 512; r += 8) acc += base[r * 32 + j];
    __shared__ float red[8][32];
    red[g][j] = acc;
    __syncthreads();
    if (tid < 32) {
        float s = 0.f;
#pragma unroll
        for (int gg = 0; gg < 8; ++gg) s += red[gg][tid];
        float pooled = s * (1.f / 512.f);
        float h = b1[tid];
#pragma unroll
        for (int i = 0; i < 32; ++i)
            h = fmaf(__shfl_sync(0xffffffffu, pooled, i), W1[i * 32 + tid], h);
        h = eluf(h);
        float t = h * W2[tid];
#pragma unroll
        for (int o = 16; o; o >>= 1) t += __shfl_down_sync(0xffffffffu, t, o);
        if (tid == 0) {
            float prob = 1.f / (1.f + expf(-(t + b2[0])));
            out[e] = prob;
            if (out_size == 2 * BB) out[BB + e] = (float)e;
            else if (out_size == 3 * BB) ((long long*)(out + BB))[e] = (long long)e;
        }
    }
}

// ---------------- launch ------------------------------------------------------
extern "C" void kernel_launch(void* const* d_in, const int* in_sizes, int n_in,
                              void* d_out, int out_size)
{
    const float* x_sv   = (const float*)d_in[0];
    const float* x_trk  = (const float*)d_in[1];
    const float* x_pfc  = (const float*)d_in[2];
    const float* sv_W1  = (const float*)d_in[6];
    const float* sv_b1  = (const float*)d_in[7];
    const float* sv_W2  = (const float*)d_in[8];
    const float* sv_b2  = (const float*)d_in[9];
    const float* trk_W1 = (const float*)d_in[10];
    const float* trk_b1 = (const float*)d_in[11];
    const float* trk_W2 = (const float*)d_in[12];
    const float* trk_b2 = (const float*)d_in[13];
    const float* pfc_W1 = (const float*)d_in[14];
    const float* pfc_b1 = (const float*)d_in[15];
    const float* pfc_W2 = (const float*)d_in[16];
    const float* pfc_b2 = (const float*)d_in[17];
    const float* conv_W = (const float*)d_in[18];
    const float* conv_b = (const float*)d_in[19];
    const float* out_W1 = (const float*)d_in[20];
    const float* out_b1 = (const float*)d_in[21];
    const float* out_W2 = (const float*)d_in[22];
    const float* out_b2 = (const float*)d_in[23];
    float* out = (float*)d_out;

    float *sv, *trk, *pfc, *U, *V, *V1, *f1, *f2, *f3;
    cudaGetSymbolAddress((void**)&sv,  g_sv);
    cudaGetSymbolAddress((void**)&trk, g_trk);
    cudaGetSymbolAddress((void**)&pfc, g_pfc);
    cudaGetSymbolAddress((void**)&U,   g_U);
    cudaGetSymbolAddress((void**)&V,   g_V);
    cudaGetSymbolAddress((void**)&V1,  g_V1);
    cudaGetSymbolAddress((void**)&f1,  g_f1);
    cudaGetSymbolAddress((void**)&f2,  g_f2);
    cudaGetSymbolAddress((void**)&f3,  g_f3);

    cudaFuncSetAttribute(knn_k, cudaFuncAttributeMaxDynamicSharedMemorySize, KNN_SMEM);

    encode_all_k<<<2176, 256>>>(x_sv, x_trk, x_pfc,
                                sv_W1, sv_b1, sv_W2, sv_b2,
                                trk_W1, trk_b1, trk_W2, trk_b2,
                                pfc_W1, pfc_b1, pfc_W2, pfc_b2,
                                sv, trk, pfc);
    lin_all_k<<<2176, 256>>>(sv, trk, pfc, V1, U, V, conv_W, conv_b);
    knn_k<<<BB * 2, 512, KNN_SMEM>>>(sv,  trk, V1, U, f1, N_SV);
    knn_k<<<BB * 2, 512, KNN_SMEM>>>(pfc, trk, V,  U, f2, N_PFC);
    lin2_k<<<2048, 256>>>(f1, f2, V, U, conv_W, conv_b);
    knn_k<<<BB * 2, 512, KNN_SMEM>>>(f1, f2, V, U, f3, N_TRK);
    pool_k<<<BB, 256>>>(f3, out_W1, out_b1, out_W2, out_b2, out, out_size);
}

// round 8
// speedup vs baseline: 1.7032x; 1.7032x over previous
#include <cuda_runtime.h>
#include <math.h>

#define BB 256
#define N_SV 64
#define N_TRK 512
#define N_PFC 512
#define KNN 8
#define HH 32

typedef unsigned long long u64;
typedef unsigned int u32;

// ---------------- scratch (static device arrays; no allocation) -------------
__device__ float g_sv [BB * N_SV  * HH];
__device__ float g_trk[BB * N_TRK * HH];
__device__ float g_pfc[BB * N_PFC * HH];
__device__ float g_U  [BB * N_TRK * HH];
__device__ float g_V  [BB * N_PFC * HH];
__device__ float g_V1 [BB * N_SV  * HH];
__device__ float g_f1 [BB * N_TRK * HH];
__device__ float g_f2 [BB * N_TRK * HH];
__device__ float g_f3 [BB * N_TRK * HH];

__device__ __forceinline__ float eluf(float x) {
    return x > 0.f ? x : (expf(x) - 1.f);
}

__device__ __forceinline__ void tf32split(float x, u32& h, u32& l) {
    asm("cvt.rna.tf32.f32 %0, %1;" : "=r"(h) : "f"(x));
    float r = x - __uint_as_float(h);
    asm("cvt.rna.tf32.f32 %0, %1;" : "=r"(l) : "f"(r));
}

__device__ __forceinline__ void mma_tf32(float& c0, float& c1, float& c2, float& c3,
                                         u32 a0, u32 a1, u32 a2, u32 a3,
                                         u32 b0, u32 b1)
{
    asm volatile(
        "mma.sync.aligned.m16n8k8.row.col.f32.tf32.tf32.f32 "
        "{%0,%1,%2,%3}, {%4,%5,%6,%7}, {%8,%9}, {%0,%1,%2,%3};"
        : "+f"(c0), "+f"(c1), "+f"(c2), "+f"(c3)
        : "r"(a0), "r"(a1), "r"(a2), "r"(a3), "r"(b0), "r"(b1));
}

// sorted ascending insert into 8-entry u64 list (sel[7] = worst kept)
#define SEL_INSERT(sel, c)                                          \
    if ((c) < sel[7]) {                                             \
        sel[7] = (c);                                               \
        _Pragma("unroll")                                           \
        for (int _p = 7; _p > 0; --_p) {                            \
            if (sel[_p] < sel[_p - 1]) {                            \
                u64 _t = sel[_p]; sel[_p] = sel[_p-1]; sel[_p-1] = _t; \
            }                                                       \
        }                                                           \
    }

// ================= fused encoder: 2-layer MLP, 128 nodes/block ==============
template <int FIN>
__device__ __forceinline__ void encode_body(
    const float* __restrict__ x,
    const float* __restrict__ W1, const float* __restrict__ b1,
    const float* __restrict__ W2, const float* __restrict__ b2,
    float* __restrict__ out, int blk,
    float* w1s, float* w2s, float* b1s, float* b2s)
{
    int tid = threadIdx.x;
    for (int i = tid; i < FIN * 32; i += 256) w1s[i] = W1[i];
    for (int i = tid; i < 1024;     i += 256) w2s[i] = W2[i];
    if (tid < 32) { b1s[tid] = b1[tid]; b2s[tid] = b2[tid]; }
    __syncthreads();

    int lane = tid & 31, wid = tid >> 5;

#pragma unroll
    for (int it = 0; it < 4; ++it) {
        int nb = blk * 128 + it * 32 + wid * 4;

        float xv0 = (lane < FIN) ? x[(size_t)(nb + 0) * FIN + lane] : 0.f;
        float xv1 = (lane < FIN) ? x[(size_t)(nb + 1) * FIN + lane] : 0.f;
        float xv2 = (lane < FIN) ? x[(size_t)(nb + 2) * FIN + lane] : 0.f;
        float xv3 = (lane < FIN) ? x[(size_t)(nb + 3) * FIN + lane] : 0.f;

        float h0 = b1s[lane], h1 = h0, h2 = h0, h3 = h0;
#pragma unroll
        for (int i = 0; i < FIN; ++i) {
            float w = w1s[i * 32 + lane];
            h0 = fmaf(__shfl_sync(0xffffffffu, xv0, i), w, h0);
            h1 = fmaf(__shfl_sync(0xffffffffu, xv1, i), w, h1);
            h2 = fmaf(__shfl_sync(0xffffffffu, xv2, i), w, h2);
            h3 = fmaf(__shfl_sync(0xffffffffu, xv3, i), w, h3);
        }
        h0 = eluf(h0); h1 = eluf(h1); h2 = eluf(h2); h3 = eluf(h3);

        float o0 = b2s[lane], o1 = o0, o2 = o0, o3 = o0;
#pragma unroll
        for (int i = 0; i < 32; ++i) {
            float w = w2s[i * 32 + lane];
            o0 = fmaf(__shfl_sync(0xffffffffu, h0, i), w, o0);
            o1 = fmaf(__shfl_sync(0xffffffffu, h1, i), w, o1);
            o2 = fmaf(__shfl_sync(0xffffffffu, h2, i), w, o2);
            o3 = fmaf(__shfl_sync(0xffffffffu, h3, i), w, o3);
        }
        out[(size_t)(nb + 0) * 32 + lane] = eluf(o0);
        out[(size_t)(nb + 1) * 32 + lane] = eluf(o1);
        out[(size_t)(nb + 2) * 32 + lane] = eluf(o2);
        out[(size_t)(nb + 3) * 32 + lane] = eluf(o3);
    }
}

__global__ void __launch_bounds__(256) encode_all_k(
    const float* x_sv, const float* x_trk, const float* x_pfc,
    const float* svW1, const float* svb1, const float* svW2, const float* svb2,
    const float* tkW1, const float* tkb1, const float* tkW2, const float* tkb2,
    const float* pfW1, const float* pfb1, const float* pfW2, const float* pfb2,
    float* o_sv, float* o_trk, float* o_pfc)
{
    __shared__ float w1s[32 * 32];
    __shared__ float w2s[32 * 32];
    __shared__ float b1s[32], b2s[32];
    int b = blockIdx.x;
    if (b < 128)
        encode_body<14>(x_sv, svW1, svb1, svW2, svb2, o_sv, b, w1s, w2s, b1s, b2s);
    else if (b < 1152)
        encode_body<30>(x_trk, tkW1, tkb1, tkW2, tkb2, o_trk, b - 128, w1s, w2s, b1s, b2s);
    else
        encode_body<10>(x_pfc, pfW1, pfb1, pfW2, pfb2, o_pfc, b - 1152, w1s, w2s, b1s, b2s);
}

// ================ fused 32x32 linear (mode 0: (Wa-Wb)+b, mode 1: Wb) ========
__device__ __forceinline__ void lin_body(
    const float* __restrict__ in, float* __restrict__ out, int blk, int mode,
    const float* __restrict__ convW, const float* __restrict__ convB,
    float* ws, float* bs)
{
    int tid = threadIdx.x;
    for (int i = tid; i < 1024; i += 256)
        ws[i] = (mode == 0) ? (convW[i] - convW[1024 + i]) : convW[1024 + i];
    if (tid < 32) bs[tid] = (mode == 0) ? convB[tid] : 0.f;
    __syncthreads();

    int lane = tid & 31, wid = tid >> 5;

#pragma unroll
    for (int it = 0; it < 4; ++it) {
        int nb = blk * 128 + it * 32 + wid * 4;

        float xv0 = in[(size_t)(nb + 0) * 32 + lane];
        float xv1 = in[(size_t)(nb + 1) * 32 + lane];
        float xv2 = in[(size_t)(nb + 2) * 32 + lane];
        float xv3 = in[(size_t)(nb + 3) * 32 + lane];
        float o0 = bs[lane], o1 = o0, o2 = o0, o3 = o0;
#pragma unroll
        for (int i = 0; i < 32; ++i) {
            float w = ws[i * 32 + lane];
            o0 = fmaf(__shfl_sync(0xffffffffu, xv0, i), w, o0);
            o1 = fmaf(__shfl_sync(0xffffffffu, xv1, i), w, o1);
            o2 = fmaf(__shfl_sync(0xffffffffu, xv2, i), w, o2);
            o3 = fmaf(__shfl_sync(0xffffffffu, xv3, i), w, o3);
        }
        out[(size_t)(nb + 0) * 32 + lane] = o0;
        out[(size_t)(nb + 1) * 32 + lane] = o1;
        out[(size_t)(nb + 2) * 32 + lane] = o2;
        out[(size_t)(nb + 3) * 32 + lane] = o3;
    }
}

__global__ void __launch_bounds__(256) lin_all_k(
    const float* sv, const float* trk, const float* pfc,
    float* V1, float* U, float* V,
    const float* convW, const float* convB)
{
    __shared__ float ws[1024];
    __shared__ float bs[32];
    int b = blockIdx.x;
    if (b < 128)        lin_body(sv,  V1, b,        1, convW, convB, ws, bs);
    else if (b < 1152)  lin_body(trk, U,  b - 128,  0, convW, convB, ws, bs);
    else                lin_body(pfc, V,  b - 1152, 1, convW, convB, ws, bs);
}

__global__ void __launch_bounds__(256) lin2_k(
    const float* f1, const float* f2, float* V, float* U,
    const float* convW, const float* convB)
{
    __shared__ float ws[1024];
    __shared__ float bs[32];
    int b = blockIdx.x;
    if (b < 1024) lin_body(f1, V, b,        1, convW, convB, ws, bs);
    else          lin_body(f2, U, b - 1024, 0, convW, convB, ws, bs);
}

// ================= kNN: mma scoring -> smem scores -> scalar selection ======
// 2 blocks/event (256 dsts), 256 threads = 8 warps; each warp owns 2 m16 dst
// tiles. MMA epilogue finalizes d2 into scores[256][67] (stride 67 == 3 mod 32
// -> scalar access conflict-free). Selection: ONE thread per dst scans its
// score row with branch-free buffered appends (single list per dst, no merge).
// Candidate u64 = (f32bits(max(d2,0)) << 32) | src_idx  (exact, stable).
#define CH       64
#define STRIDE   67
#define CAPK     8
#define SM_SCORES 0
#define SM_HI    68608
#define SM_LO    (68608 + 9216)
#define SM_SQ    (68608 + 18432)
#define SM_SD    (SM_SQ + 256)
#define SM_BUF   (SM_SD + 1024)
#define KNN_SMEM (SM_BUF + 256 * CAPK * 8)

__device__ __forceinline__ void flush_u64(const u64* mybuf, int& cnt, u64 (&sel)[8])
{
    for (int i = 0; i < cnt; ++i) {
        u64 c = mybuf[i];
        SEL_INSERT(sel, c);
    }
    cnt = 0;
}

__global__ void __launch_bounds__(256, 2) knn_k(
                      const float* __restrict__ src_enc,
                      const float* __restrict__ dst_enc,
                      const float* __restrict__ V,
                      const float* __restrict__ U,
                      float* __restrict__ out, int Ns)
{
    extern __shared__ char smraw[];
    float* scores  = (float*)(smraw + SM_SCORES);   // [256][67]
    float* srcT_hi = (float*)(smraw + SM_HI);       // [32][72]
    float* srcT_lo = (float*)(smraw + SM_LO);       // [32][72]
    float* sqs     = (float*)(smraw + SM_SQ);       // [64]
    float* sds     = (float*)(smraw + SM_SD);       // [256]
    u64*   buf     = (u64*)(smraw + SM_BUF);        // [256][CAPK]
    int*   idxs    = (int*)(smraw + SM_HI);         // overlay (after last mma)

    int tid  = threadIdx.x;
    int lane = tid & 31;
    int w    = tid >> 5;          // 0..7
    int e    = blockIdx.x >> 1;
    int half = blockIdx.x & 1;
    int g    = lane >> 2;         // 0..7
    int c4   = lane & 3;          // 0..3

    const float* sbase = src_enc + (size_t)e * Ns * 32;
    int dstblk = half * 256;                     // block-local dst base in event
    const float* dbase = dst_enc + ((size_t)e * 512 + dstblk + w * 32) * 32;

    // ---- per-thread dst squared norm ----
    {
        const float4* myrow = (const float4*)(dst_enc + ((size_t)e * 512 + dstblk + tid) * 32);
        float s = 0.f;
#pragma unroll
        for (int q = 0; q < 8; ++q) {
            float4 v = myrow[q];
            s = fmaf(v.x, v.x, s); s = fmaf(v.y, v.y, s);
            s = fmaf(v.z, v.z, s); s = fmaf(v.w, v.w, s);
        }
        sds[tid] = s;
    }

    // ---- A fragments: 2 tiles (rows 0..15 and 16..31 of warp's 32 dsts) ----
    u32 ahiA[16], aloA[16], ahiB[16], aloB[16];
#pragma unroll
    for (int j = 0; j < 4; ++j) {
        int k = 8 * j + c4;
        tf32split(dbase[g * 32 + k],            ahiA[4*j+0], aloA[4*j+0]);
        tf32split(dbase[(g + 8) * 32 + k],      ahiA[4*j+1], aloA[4*j+1]);
        tf32split(dbase[g * 32 + k + 4],        ahiA[4*j+2], aloA[4*j+2]);
        tf32split(dbase[(g + 8) * 32 + k + 4],  ahiA[4*j+3], aloA[4*j+3]);
        tf32split(dbase[(16 + g) * 32 + k],     ahiB[4*j+0], aloB[4*j+0]);
        tf32split(dbase[(24 + g) * 32 + k],     ahiB[4*j+1], aloB[4*j+1]);
        tf32split(dbase[(16 + g) * 32 + k + 4], ahiB[4*j+2], aloB[4*j+2]);
        tf32split(dbase[(24 + g) * 32 + k + 4], ahiB[4*j+3], aloB[4*j+3]);
    }
    __syncthreads();

    float sdA0 = sds[w * 32 + g],      sdA1 = sds[w * 32 + 8 + g];
    float sdB0 = sds[w * 32 + 16 + g], sdB1 = sds[w * 32 + 24 + g];

    u64 sel[8];
#pragma unroll
    for (int k = 0; k < 8; ++k) sel[k] = ~0ull;
    int cnt = 0;
    u64* mybuf = buf + (size_t)tid * CAPK;
    unsigned buf_sa = (unsigned)__cvta_generic_to_shared(mybuf);

    int rowA0 = (w * 32 + g) * STRIDE,      rowA1 = (w * 32 + 8 + g) * STRIDE;
    int rowB0 = (w * 32 + 16 + g) * STRIDE, rowB1 = (w * 32 + 24 + g) * STRIDE;
    int myrowbase = tid * STRIDE;

    int nch = (Ns + CH - 1) / CH;
    for (int ch = 0; ch < nch; ++ch) {
        int cbase = ch * CH;

        __syncthreads();
        // ---- stage 64 srcs: tf32-split transpose + squared norms ----
        for (int sl = w; sl < CH; sl += 8) {
            float x = sbase[(size_t)(cbase + sl) * 32 + lane];
            u32 h, l;
            tf32split(x, h, l);
            srcT_hi[lane * 72 + sl] = __uint_as_float(h);
            srcT_lo[lane * 72 + sl] = __uint_as_float(l);
            float v = x * x;
#pragma unroll
            for (int o = 16; o; o >>= 1) v += __shfl_xor_sync(0xffffffffu, v, o);
            if (lane == 0) sqs[sl] = v;
        }
        __syncthreads();

        // ---- MMA: 8 src-subtiles x 2 dst tiles; finalize d2 into scores ----
#pragma unroll
        for (int st = 0; st < CH / 8; ++st) {
            int sl0 = st << 3;
            float a0 = 0.f, a1 = 0.f, a2 = 0.f, a3 = 0.f;
            float b0 = 0.f, b1 = 0.f, b2 = 0.f, b3 = 0.f;
#pragma unroll
            for (int j = 0; j < 4; ++j) {
                int k = 8 * j + c4;
                int off = k * 72 + sl0 + g;
                u32 bh0 = __float_as_uint(srcT_hi[off]);
                u32 bh1 = __float_as_uint(srcT_hi[off + 4 * 72]);
                u32 bl0 = __float_as_uint(srcT_lo[off]);
                u32 bl1 = __float_as_uint(srcT_lo[off + 4 * 72]);
                mma_tf32(a0, a1, a2, a3, ahiA[4*j+0], ahiA[4*j+1], ahiA[4*j+2], ahiA[4*j+3], bh0, bh1);
                mma_tf32(a0, a1, a2, a3, ahiA[4*j+0], ahiA[4*j+1], ahiA[4*j+2], ahiA[4*j+3], bl0, bl1);
                mma_tf32(a0, a1, a2, a3, aloA[4*j+0], aloA[4*j+1], aloA[4*j+2], aloA[4*j+3], bh0, bh1);
                mma_tf32(b0, b1, b2, b3, ahiB[4*j+0], ahiB[4*j+1], ahiB[4*j+2], ahiB[4*j+3], bh0, bh1);
                mma_tf32(b0, b1, b2, b3, ahiB[4*j+0], ahiB[4*j+1], ahiB[4*j+2], ahiB[4*j+3], bl0, bl1);
                mma_tf32(b0, b1, b2, b3, aloB[4*j+0], aloB[4*j+1], aloB[4*j+2], aloB[4*j+3], bh0, bh1);
            }
            float2 sqp = *(const float2*)(sqs + sl0 + 2 * c4);
            int col = sl0 + 2 * c4;
            scores[rowA0 + col]     = fmaxf(fmaf(-2.f, a0, sdA0 + sqp.x), 0.f);
            scores[rowA0 + col + 1] = fmaxf(fmaf(-2.f, a1, sdA0 + sqp.y), 0.f);
            scores[rowA1 + col]     = fmaxf(fmaf(-2.f, a2, sdA1 + sqp.x), 0.f);
            scores[rowA1 + col + 1] = fmaxf(fmaf(-2.f, a3, sdA1 + sqp.y), 0.f);
            scores[rowB0 + col]     = fmaxf(fmaf(-2.f, b0, sdB0 + sqp.x), 0.f);
            scores[rowB0 + col + 1] = fmaxf(fmaf(-2.f, b1, sdB0 + sqp.y), 0.f);
            scores[rowB1 + col]     = fmaxf(fmaf(-2.f, b2, sdB1 + sqp.x), 0.f);
            scores[rowB1 + col + 1] = fmaxf(fmaf(-2.f, b3, sdB1 + sqp.y), 0.f);
        }
        __syncthreads();

        // ---- selection: thread per dst, branch-free buffered appends ----
        for (int sl = 0; sl < CH; sl += 4) {
            float v0 = scores[myrowbase + sl];
            float v1 = scores[myrowbase + sl + 1];
            float v2 = scores[myrowbase + sl + 2];
            float v3 = scores[myrowbase + sl + 3];
            u64 p0 = ((u64)__float_as_uint(v0) << 32) | (u32)(cbase + sl);
            u64 p1 = ((u64)__float_as_uint(v1) << 32) | (u32)(cbase + sl + 1);
            u64 p2 = ((u64)__float_as_uint(v2) << 32) | (u32)(cbase + sl + 2);
            u64 p3 = ((u64)__float_as_uint(v3) << 32) | (u32)(cbase + sl + 3);

            asm volatile("{.reg .pred p; setp.lt.u64 p, %1, %2; @p st.shared.b64 [%0], %1;}"
                :: "r"(buf_sa + (unsigned)cnt * 8u), "l"(p0), "l"(sel[7]) : "memory");
            cnt += (p0 < sel[7]) ? 1 : 0;
            asm volatile("{.reg .pred p; setp.lt.u64 p, %1, %2; @p st.shared.b64 [%0], %1;}"
                :: "r"(buf_sa + (unsigned)cnt * 8u), "l"(p1), "l"(sel[7]) : "memory");
            cnt += (p1 < sel[7]) ? 1 : 0;
            asm volatile("{.reg .pred p; setp.lt.u64 p, %1, %2; @p st.shared.b64 [%0], %1;}"
                :: "r"(buf_sa + (unsigned)cnt * 8u), "l"(p2), "l"(sel[7]) : "memory");
            cnt += (p2 < sel[7]) ? 1 : 0;
            asm volatile("{.reg .pred p; setp.lt.u64 p, %1, %2; @p st.shared.b64 [%0], %1;}"
                :: "r"(buf_sa + (unsigned)cnt * 8u), "l"(p3), "l"(sel[7]) : "memory");
            cnt += (p3 < sel[7]) ? 1 : 0;

            // <=4 appends/group; flush keeps cnt <= CAPK-4 at group entry
            if (__any_sync(0xffffffffu, cnt >= CAPK - 3)) {
                flush_u64(mybuf, cnt, sel);
            }
        }
    }
    flush_u64(mybuf, cnt, sel);

#pragma unroll
    for (int k = 0; k < 8; ++k)
        idxs[tid * 8 + k] = (int)(u32)sel[k];
    __syncthreads();

    // ---- aggregation: warp per dst, coalesced V gathers ----
    const float* Ve = V + (size_t)e * Ns * 32;
    for (int dd = w; dd < 256; dd += 8) {
        int dg = e * 512 + dstblk + dd;
        float mx = -3.4e38f;
#pragma unroll
        for (int k = 0; k < KNN; ++k) {
            int s = idxs[dd * 8 + k];
            mx = fmaxf(mx, Ve[s * 32 + lane]);
        }
        out[(size_t)dg * 32 + lane] = eluf(U[(size_t)dg * 32 + lane] + mx);
    }
}

// ---------------- mean pool + head MLP + sigmoid -----------------------------
__global__ void pool_k(const float* __restrict__ f3,
                       const float* __restrict__ W1, const float* __restrict__ b1,
                       const float* __restrict__ W2, const float* __restrict__ b2,
                       float* __restrict__ out, int out_size)
{
    int e = blockIdx.x;
    int tid = threadIdx.x;
    int j = tid & 31, g = tid >> 5;
    const float* base = f3 + (size_t)e * 512 * 32;
    float acc = 0.f;
    for (int r = g; r < 512; r += 8) acc += base[r * 32 + j];
    __shared__ float red[8][32];
    red[g][j] = acc;
    __syncthreads();
    if (tid < 32) {
        float s = 0.f;
#pragma unroll
        for (int gg = 0; gg < 8; ++gg) s += red[gg][tid];
        float pooled = s * (1.f / 512.f);
        float h = b1[tid];
#pragma unroll
        for (int i = 0; i < 32; ++i)
            h = fmaf(__shfl_sync(0xffffffffu, pooled, i), W1[i * 32 + tid], h);
        h = eluf(h);
        float t = h * W2[tid];
#pragma unroll
        for (int o = 16; o; o >>= 1) t += __shfl_down_sync(0xffffffffu, t, o);
        if (tid == 0) {
            float prob = 1.f / (1.f + expf(-(t + b2[0])));
            out[e] = prob;
            if (out_size == 2 * BB) out[BB + e] = (float)e;
            else if (out_size == 3 * BB) ((long long*)(out + BB))[e] = (long long)e;
        }
    }
}

// ---------------- launch ------------------------------------------------------
extern "C" void kernel_launch(void* const* d_in, const int* in_sizes, int n_in,
                              void* d_out, int out_size)
{
    const float* x_sv   = (const float*)d_in[0];
    const float* x_trk  = (const float*)d_in[1];
    const float* x_pfc  = (const float*)d_in[2];
    const float* sv_W1  = (const float*)d_in[6];
    const float* sv_b1  = (const float*)d_in[7];
    const float* sv_W2  = (const float*)d_in[8];
    const float* sv_b2  = (const float*)d_in[9];
    const float* trk_W1 = (const float*)d_in[10];
    const float* trk_b1 = (const float*)d_in[11];
    const float* trk_W2 = (const float*)d_in[12];
    const float* trk_b2 = (const float*)d_in[13];
    const float* pfc_W1 = (const float*)d_in[14];
    const float* pfc_b1 = (const float*)d_in[15];
    const float* pfc_W2 = (const float*)d_in[16];
    const float* pfc_b2 = (const float*)d_in[17];
    const float* conv_W = (const float*)d_in[18];
    const float* conv_b = (const float*)d_in[19];
    const float* out_W1 = (const float*)d_in[20];
    const float* out_b1 = (const float*)d_in[21];
    const float* out_W2 = (const float*)d_in[22];
    const float* out_b2 = (const float*)d_in[23];
    float* out = (float*)d_out;

    float *sv, *trk, *pfc, *U, *V, *V1, *f1, *f2, *f3;
    cudaGetSymbolAddress((void**)&sv,  g_sv);
    cudaGetSymbolAddress((void**)&trk, g_trk);
    cudaGetSymbolAddress((void**)&pfc, g_pfc);
    cudaGetSymbolAddress((void**)&U,   g_U);
    cudaGetSymbolAddress((void**)&V,   g_V);
    cudaGetSymbolAddress((void**)&V1,  g_V1);
    cudaGetSymbolAddress((void**)&f1,  g_f1);
    cudaGetSymbolAddress((void**)&f2,  g_f2);
    cudaGetSymbolAddress((void**)&f3,  g_f3);

    cudaFuncSetAttribute(knn_k, cudaFuncAttributeMaxDynamicSharedMemorySize, KNN_SMEM);

    encode_all_k<<<2176, 256>>>(x_sv, x_trk, x_pfc,
                                sv_W1, sv_b1, sv_W2, sv_b2,
                                trk_W1, trk_b1, trk_W2, trk_b2,
                                pfc_W1, pfc_b1, pfc_W2, pfc_b2,
                                sv, trk, pfc);
    lin_all_k<<<2176, 256>>>(sv, trk, pfc, V1, U, V, conv_W, conv_b);
    knn_k<<<BB * 2, 256, KNN_SMEM>>>(sv,  trk, V1, U, f1, N_SV);
    knn_k<<<BB * 2, 256, KNN_SMEM>>>(pfc, trk, V,  U, f2, N_PFC);
    lin2_k<<<2048, 256>>>(f1, f2, V, U, conv_W, conv_b);
    knn_k<<<BB * 2, 256, KNN_SMEM>>>(f1, f2, V, U, f3, N_TRK);
    pool_k<<<BB, 256>>>(f3, out_W1, out_b1, out_W2, out_b2, out, out_size);
}